// round 8
// baseline (speedup 1.0000x reference)
#include <cuda_runtime.h>
#include <cuda_bf16.h>

// FilterLayer: out = irfft(rfft(x, ortho)*W, ortho) + x over last dim (L=12)
// == per-node circulant matvec: y[t] = sum_j h[n][(t-j) mod 12] * x[j],
// residual identity folded into tap d=0.
//
// R8: single graph node. Measured facts: the apply body (R1) runs at the
// chip LTS ceiling (~6.2TB/s) and cannot be beaten structurally (5 attempts);
// the remaining ~5.6us was build-kernel launch + graph serialization. Here
// block 0 builds the 207x12 fp32 tap table in-kernel and releases a flag;
// other blocks issue their x loads first, then acquire-spin (nanosleep
// backoff), then run the unchanged apply body. A done-counter makes the
// last block reset the flag so every graph replay starts clean.

#define SEQ 12
#define NODES 207
#define NFREQ 7
#define NTAPS (NODES * SEQ)          // 2484
#define TPB 256

__device__ __align__(16) float g_H[NTAPS];
__device__ int g_flag = 0;           // taps-ready flag
__device__ unsigned int g_done = 0;  // per-replay completion counter

__device__ __constant__ float f_COS[12] = {
    1.0f,  0.8660254037844387f,  0.5f,  0.0f, -0.5f, -0.8660254037844387f,
   -1.0f, -0.8660254037844387f, -0.5f,  0.0f,  0.5f,  0.8660254037844387f
};
__device__ __constant__ float f_SIN[12] = {
    0.0f,  0.5f,  0.8660254037844387f,  1.0f,  0.8660254037844387f,  0.5f,
    0.0f, -0.5f, -0.8660254037844387f, -1.0f, -0.8660254037844387f, -0.5f
};

__global__ void __launch_bounds__(TPB) filter_fused_kernel(
    const float4* __restrict__ x,
    const float*  __restrict__ w,     // [207][7][2]
    float4* __restrict__ out)
{
    const int tid = threadIdx.x;
    const int r   = blockIdx.x * TPB + tid;   // one row per thread, exact grid

    // Issue this thread's row loads immediately (independent of taps).
    const size_t g = (size_t)r * 3;
    const float4 a = __ldg(x + g + 0);
    const float4 b = __ldg(x + g + 1);
    const float4 c = __ldg(x + g + 2);

    if (blockIdx.x == 0) {
        // ---- producer: build taps, one node per thread (tid < 207) ----
        if (tid < NODES) {
            const float* wn = w + tid * (NFREQ * 2);
            const float w0  = wn[0];
            const float w6r = wn[12];
            float wr[6], wi[6];
            #pragma unroll
            for (int k = 1; k <= 5; k++) {
                wr[k] =  2.0f * wn[2 * k];
                wi[k] = -2.0f * wn[2 * k + 1];
            }
            float t[SEQ];
            #pragma unroll
            for (int d = 0; d < SEQ; d++) {
                float acc = w0 + ((d & 1) ? -w6r : w6r);
                #pragma unroll
                for (int k = 1; k <= 5; k++) {
                    const int m = (k * d) % 12;           // compile-time
                    acc = fmaf(wr[k], f_COS[m], acc);
                    acc = fmaf(wi[k], f_SIN[m], acc);
                }
                t[d] = acc * (1.0f / 12.0f);
            }
            t[0] += 1.0f;   // fold residual identity
            float4* dst = reinterpret_cast<float4*>(g_H + tid * SEQ);
            dst[0] = make_float4(t[0], t[1], t[2],  t[3]);
            dst[1] = make_float4(t[4], t[5], t[6],  t[7]);
            dst[2] = make_float4(t[8], t[9], t[10], t[11]);
        }
        __syncthreads();
        if (tid == 0) {
            __threadfence();                 // publish g_H
            atomicExch(&g_flag, 1);          // release
        }
    } else {
        // ---- consumers: acquire-spin until taps are published ----
        if (tid == 0) {
            while (atomicAdd(&g_flag, 0) == 0) __nanosleep(64);
        }
        __syncthreads();
        __threadfence();                     // acquire ordering for g_H reads
    }

    // ---- R1 apply body (unchanged; runs at the LTS ceiling) ----
    const int n = r % NODES;
    const float4* Hv = reinterpret_cast<const float4*>(g_H + n * SEQ);
    const float4 h0 = Hv[0];
    const float4 h1 = Hv[1];
    const float4 h2 = Hv[2];
    const float h[SEQ] = { h0.x, h0.y, h0.z, h0.w,
                           h1.x, h1.y, h1.z, h1.w,
                           h2.x, h2.y, h2.z, h2.w };

    const float xv[SEQ] = { a.x, a.y, a.z, a.w,
                            b.x, b.y, b.z, b.w,
                            c.x, c.y, c.z, c.w };

    float y[SEQ];
    #pragma unroll
    for (int t = 0; t < SEQ; t++) {
        float s = 0.0f;
        #pragma unroll
        for (int j = 0; j < SEQ; j++)
            s = fmaf(h[(t - j + SEQ) % SEQ], xv[j], s);   // compile-time index
        y[t] = s;
    }

    out[g + 0] = make_float4(y[0], y[1], y[2],  y[3]);
    out[g + 1] = make_float4(y[4], y[5], y[6],  y[7]);
    out[g + 2] = make_float4(y[8], y[9], y[10], y[11]);

    // ---- replay-safe reset: last finished block clears the flag ----
    __syncthreads();
    if (tid == 0) {
        __threadfence();
        const unsigned int t = atomicAdd(&g_done, 1u);
        if (t == gridDim.x - 1u) {
            g_done = 0u;
            g_flag = 0;
            __threadfence();
        }
    }
}

extern "C" void kernel_launch(void* const* d_in, const int* in_sizes, int n_in,
                              void* d_out, int out_size) {
    const float* x = (const float*)d_in[0];   // [1024,32,207,12] fp32
    const float* w = (const float*)d_in[1];   // [1,207,7,2] fp32

    const int nrows = out_size / SEQ;         // 6,782,976 = 26496 * 256 exactly
    const int blocks = (nrows + TPB - 1) / TPB;
    filter_fused_kernel<<<blocks, TPB>>>(
        reinterpret_cast<const float4*>(x),
        w,
        reinterpret_cast<float4*>(d_out));
}

// round 9
// speedup vs baseline: 1.5025x; 1.5025x over previous
#include <cuda_runtime.h>
#include <cuda_bf16.h>

// FilterLayer: out = irfft(rfft(x, ortho)*W, ortho) + x over last dim (L=12)
// == per-node circulant matvec: y[t] = sum_j h[n][(t-j) mod 12] * x[j],
// residual identity folded into tap d=0.
//
// R9: two graph nodes, gap minimized.
//  - build kernel: fp32, ONE block, one node per thread (207 active), and it
//    fires cudaTriggerProgrammaticLaunchCompletion() at entry so the apply
//    grid starts dispatching immediately (PDL).
//  - apply kernel: R1's body verbatim (96.8us, at the chip LTS ceiling);
//    issues x loads, then cudaGridDependencySynchronize(), then taps.

#define SEQ 12
#define NODES 207
#define NFREQ 7
#define NTAPS (NODES * SEQ)          // 2484
#define TPB 256

__device__ __align__(16) float g_H[NTAPS];

__device__ __constant__ float f_COS[12] = {
    1.0f,  0.8660254037844387f,  0.5f,  0.0f, -0.5f, -0.8660254037844387f,
   -1.0f, -0.8660254037844387f, -0.5f,  0.0f,  0.5f,  0.8660254037844387f
};
__device__ __constant__ float f_SIN[12] = {
    0.0f,  0.5f,  0.8660254037844387f,  1.0f,  0.8660254037844387f,  0.5f,
    0.0f, -0.5f, -0.8660254037844387f, -1.0f, -0.8660254037844387f, -0.5f
};

__global__ void __launch_bounds__(TPB) build_taps_kernel(
    const float* __restrict__ w /*[207][7][2]*/)
{
#if __CUDA_ARCH__ >= 900
    // Let the dependent apply grid begin dispatching right away; its
    // cudaGridDependencySynchronize() still waits for our completion.
    cudaTriggerProgrammaticLaunchCompletion();
#endif
    const int n = threadIdx.x;
    if (n >= NODES) return;

    const float* wn = w + n * (NFREQ * 2);
    const float w0  = __ldg(wn + 0);
    const float w6r = __ldg(wn + 12);
    float wr[6], wi[6];
    #pragma unroll
    for (int k = 1; k <= 5; k++) {
        wr[k] =  2.0f * __ldg(wn + 2 * k);
        wi[k] = -2.0f * __ldg(wn + 2 * k + 1);
    }
    float t[SEQ];
    #pragma unroll
    for (int d = 0; d < SEQ; d++) {
        float acc = w0 + ((d & 1) ? -w6r : w6r);
        #pragma unroll
        for (int k = 1; k <= 5; k++) {
            const int m = (k * d) % 12;            // compile-time
            acc = fmaf(wr[k], f_COS[m], acc);
            acc = fmaf(wi[k], f_SIN[m], acc);
        }
        t[d] = acc * (1.0f / 12.0f);
    }
    t[0] += 1.0f;                                  // fold residual identity

    float4* dst = reinterpret_cast<float4*>(g_H + n * SEQ);
    dst[0] = make_float4(t[0], t[1], t[2],  t[3]);
    dst[1] = make_float4(t[4], t[5], t[6],  t[7]);
    dst[2] = make_float4(t[8], t[9], t[10], t[11]);
}

__global__ void __launch_bounds__(TPB) filter_apply_kernel(
    const float4* __restrict__ x, float4* __restrict__ out)
{
    const int r = blockIdx.x * TPB + threadIdx.x;   // one row per thread

    // x loads are independent of the build kernel — issue before grid sync.
    const size_t g = (size_t)r * 3;
    const float4 a = __ldg(x + g + 0);
    const float4 b = __ldg(x + g + 1);
    const float4 c = __ldg(x + g + 2);

#if __CUDA_ARCH__ >= 900
    cudaGridDependencySynchronize();   // taps ready beyond this point
#endif

    const int n = r % NODES;
    const float4* Hv = reinterpret_cast<const float4*>(g_H + n * SEQ);
    const float4 h0 = __ldg(Hv + 0);
    const float4 h1 = __ldg(Hv + 1);
    const float4 h2 = __ldg(Hv + 2);
    const float h[SEQ] = { h0.x, h0.y, h0.z, h0.w,
                           h1.x, h1.y, h1.z, h1.w,
                           h2.x, h2.y, h2.z, h2.w };

    const float xv[SEQ] = { a.x, a.y, a.z, a.w,
                            b.x, b.y, b.z, b.w,
                            c.x, c.y, c.z, c.w };

    float y[SEQ];
    #pragma unroll
    for (int t = 0; t < SEQ; t++) {
        float s = 0.0f;
        #pragma unroll
        for (int j = 0; j < SEQ; j++)
            s = fmaf(h[(t - j + SEQ) % SEQ], xv[j], s);   // compile-time index
        y[t] = s;
    }

    out[g + 0] = make_float4(y[0], y[1], y[2],  y[3]);
    out[g + 1] = make_float4(y[4], y[5], y[6],  y[7]);
    out[g + 2] = make_float4(y[8], y[9], y[10], y[11]);
}

extern "C" void kernel_launch(void* const* d_in, const int* in_sizes, int n_in,
                              void* d_out, int out_size) {
    const float* x = (const float*)d_in[0];   // [1024,32,207,12] fp32
    const float* w = (const float*)d_in[1];   // [1,207,7,2] fp32

    build_taps_kernel<<<1, TPB>>>(w);

    const int nrows = out_size / SEQ;         // 6,782,976 = 26496 * 256 exactly
    const int blocks = (nrows + TPB - 1) / TPB;

    const float4* x4 = reinterpret_cast<const float4*>(x);
    float4* o4 = reinterpret_cast<float4*>(d_out);

    // PDL launch: apply grid may begin dispatch while build runs; the
    // device-side cudaGridDependencySynchronize provides ordering.
    cudaLaunchConfig_t cfg = {};
    cfg.gridDim  = dim3((unsigned)blocks, 1, 1);
    cfg.blockDim = dim3(TPB, 1, 1);
    cfg.dynamicSmemBytes = 0;
    cfg.stream = 0;
    cudaLaunchAttribute attr[1];
    attr[0].id = cudaLaunchAttributeProgrammaticStreamSerialization;
    attr[0].val.programmaticStreamSerializationAllowed = 1;
    cfg.attrs = attr;
    cfg.numAttrs = 1;

    cudaError_t e = cudaLaunchKernelEx(&cfg, filter_apply_kernel, x4, o4);
    if (e != cudaSuccess) {
        filter_apply_kernel<<<blocks, TPB>>>(x4, o4);   // correct fallback
    }
}